// round 4
// baseline (speedup 1.0000x reference)
#include <cuda_runtime.h>
#include <math.h>

// ---------------------------------------------------------------------------
// HanningTemplateLayer == single fused 80-tap FIR (coeffs computed in-block):
//   out[b,j] = sum_{t=0..79} c[t] * x[b, j+t-40]   (zero padded)
//   c[t]     = sum_w softmax(tw)_w * hann_{2w}[(t-40)+w],  w in {10,20,30,40}
// Two batch rows packed per fma.rn.f32x2 lane.
// Shared tile uses stride-9 padding (i -> i + (i>>3)): conflict-free strided
// window reads with pure immediate-offset LDS (no swizzle ALU).
// ---------------------------------------------------------------------------

#define THREADS 128
#define VOUT    8                  // outputs per thread (per row)
#define RING    10                 // window ring depth (VOUT + 2 prefetch)
#define TILE    (THREADS * VOUT)   // 1024 columns per block
#define TAPS    80
#define HALF    40
#define NLOG    (TILE + TAPS)      // 1104 logical float2 entries
#define NQUAD   (NLOG / 4)         // 276
#define NPHYS   (NLOG + NLOG / 8 + 8)
#define LASTWIN (TAPS - 2 + VOUT)  // last window entry consumed (86)

typedef unsigned long long ull;

__global__ __launch_bounds__(THREADS, 10)
void fir80_kernel(const float* __restrict__ x, const float* __restrict__ tw,
                  float* __restrict__ out, int L) {
    __shared__ __align__(16) float2 sx[NPHYS];   // padded, interleaved row pair
    __shared__ __align__(16) float2 sc[TAPS];    // (c,c) duplicated coeffs

    const int tid  = threadIdx.x;
    const int rp   = blockIdx.y;            // row pair index
    const int col0 = blockIdx.x * TILE;

    // ---- tile fill FIRST (get LDGs in flight), quads via LDG.128 ---------
    const float* __restrict__ xa = x + (size_t)(2 * rp) * L;
    const float* __restrict__ xb = xa + L;
    #pragma unroll
    for (int it = 0; it < 3; ++it) {
        int q = tid + it * THREADS;
        if (q < NQUAD) {
            int i = q * 4;                    // logical index, 4-aligned
            int g = col0 - HALF + i;          // 4-aligned (40, L mult of 4)
            float4 a = make_float4(0.f, 0.f, 0.f, 0.f);
            float4 b = make_float4(0.f, 0.f, 0.f, 0.f);
            if (g >= 0 && g + 3 < L) {        // quads are fully in or out
                a = *reinterpret_cast<const float4*>(xa + g);
                b = *reinterpret_cast<const float4*>(xb + g);
            }
            int ph = i + (i >> 3);            // padded physical index
            sx[ph    ] = make_float2(a.x, b.x);
            sx[ph + 1] = make_float2(a.y, b.y);
            sx[ph + 2] = make_float2(a.z, b.z);
            sx[ph + 3] = make_float2(a.w, b.w);
        }
    }

    // ---- coefficients (threads 0..79) overlap the fill latency -----------
    if (tid < TAPS) {
        float w0 = tw[0], w1 = tw[1], w2 = tw[2], w3 = tw[3];
        float m  = fmaxf(fmaxf(w0, w1), fmaxf(w2, w3));
        float e0 = expf(w0 - m), e1 = expf(w1 - m);
        float e2 = expf(w2 - m), e3 = expf(w3 - m);
        float s  = 1.0f / (e0 + e1 + e2 + e3);
        float p[4] = { e0 * s, e1 * s, e2 * s, e3 * s };
        const int widths[4] = { 10, 20, 30, 40 };
        int d = tid - HALF;
        float c = 0.0f;
        #pragma unroll
        for (int i = 0; i < 4; ++i) {
            int w = widths[i];
            int k = d + w;
            if (k >= 0 && k < 2 * w) {
                float h = 0.5f - 0.5f * cosf(6.283185307179586f * (float)k
                                             / (float)(2 * w - 1));
                c = fmaf(p[i], h, c);
            }
        }
        sc[tid] = make_float2(c, c);
    }
    __syncthreads();

    // ---- 80-tap FIR, sliding register ring, immediate-offset LDS ---------
    const ull* __restrict__ P =
        reinterpret_cast<const ull*>(sx) + 9 * tid;      // thread window base
    const ulonglong2* __restrict__ scq =
        reinterpret_cast<const ulonglong2*>(sc);         // 2 taps per LDS.128

    ull acc[VOUT];
    ull win[RING];
    #pragma unroll
    for (int v = 0; v < VOUT; ++v) acc[v] = 0ull;
    #pragma unroll
    for (int j = 0; j < RING; ++j) win[j] = P[j + (j >> 3)];

    // Invariant at tap t: win[(t+i) % RING] == X[lo + t + i], i in [0, RING)
    #pragma unroll
    for (int t = 0; t < TAPS; t += 2) {
        ulonglong2 cq = scq[t >> 1];          // (c[t] dup, c[t+1] dup)
        #pragma unroll
        for (int v = 0; v < VOUT; ++v)
            asm("fma.rn.f32x2 %0, %1, %2, %0;"
                : "+l"(acc[v]) : "l"(win[(t + v) % RING]), "l"(cq.x));
        if (t + RING <= LASTWIN)
            win[t % RING] = P[(t + RING) + ((t + RING) >> 3)];
        #pragma unroll
        for (int v = 0; v < VOUT; ++v)
            asm("fma.rn.f32x2 %0, %1, %2, %0;"
                : "+l"(acc[v]) : "l"(win[(t + 1 + v) % RING]), "l"(cq.y));
        if (t + 1 + RING <= LASTWIN)
            win[(t + 1) % RING] = P[(t + 1 + RING) + ((t + 1 + RING) >> 3)];
    }

    // ---- unpack + store (float4 built in place, low live range) ----------
    float* oa = out + (size_t)(2 * rp)     * L + col0 + tid * VOUT;
    float* ob = out + (size_t)(2 * rp + 1) * L + col0 + tid * VOUT;
    #pragma unroll
    for (int v = 0; v < VOUT; v += 4) {
        float4 qa, qb;
        asm("mov.b64 {%0, %1}, %2;" : "=f"(qa.x), "=f"(qb.x) : "l"(acc[v]));
        asm("mov.b64 {%0, %1}, %2;" : "=f"(qa.y), "=f"(qb.y) : "l"(acc[v+1]));
        asm("mov.b64 {%0, %1}, %2;" : "=f"(qa.z), "=f"(qb.z) : "l"(acc[v+2]));
        asm("mov.b64 {%0, %1}, %2;" : "=f"(qa.w), "=f"(qb.w) : "l"(acc[v+3]));
        *reinterpret_cast<float4*>(oa + v) = qa;
        *reinterpret_cast<float4*>(ob + v) = qb;
    }
}

extern "C" void kernel_launch(void* const* d_in, const int* in_sizes, int n_in,
                              void* d_out, int out_size) {
    const float* x  = (const float*)d_in[0];   // [B, L] fp32
    const float* tw = (const float*)d_in[1];   // [4] fp32
    float* out = (float*)d_out;

    const int L = 65536;
    const int B = in_sizes[0] / L;             // 64

    dim3 grid(L / TILE, B / 2);                // (64, 32) = 2048 blocks
    fir80_kernel<<<grid, THREADS>>>(x, tw, out, L);
}